// round 1
// baseline (speedup 1.0000x reference)
#include <cuda_runtime.h>

#define EPSF 1e-6f
#define MAXPTS 24
#define TPB 256

__device__ double g_acc;

__global__ void pil_init_kernel() { g_acc = 0.0; }

__global__ void pil_finalize_kernel(float* out, int n) {
    out[0] = (float)(g_acc / (double)n);
}

__global__ __launch_bounds__(TPB)
void poly_iou_kernel(const float* __restrict__ pred,
                     const float* __restrict__ tgt,
                     int n) {
    int i = blockIdx.x * blockDim.x + threadIdx.x;
    float loss = 0.0f;

    if (i < n) {
        // Vectorized loads: each poly is 8 contiguous floats.
        float4 a0 = reinterpret_cast<const float4*>(pred)[2 * i];
        float4 a1 = reinterpret_cast<const float4*>(pred)[2 * i + 1];
        float4 b0 = reinterpret_cast<const float4*>(tgt)[2 * i];
        float4 b1 = reinterpret_cast<const float4*>(tgt)[2 * i + 1];

        float p1x[4] = {a0.x, a0.z, a1.x, a1.z};
        float p1y[4] = {a0.y, a0.w, a1.y, a1.w};
        float p2x[4] = {b0.x, b0.z, b1.x, b1.z};
        float p2y[4] = {b0.y, b0.w, b1.y, b1.w};

        // Shoelace areas: sum x_k*y_{k-1} - x_{k-1}*y_k  (matches roll(+1)).
        float s1 = 0.0f, s2 = 0.0f;
        #pragma unroll
        for (int k = 0; k < 4; k++) {
            int km = (k + 3) & 3;
            s1 += p1x[k] * p1y[km] - p1x[km] * p1y[k];
            s2 += p2x[k] * p2y[km] - p2x[km] * p2y[k];
        }
        float area1 = 0.5f * fabsf(s1);
        float area2 = 0.5f * fabsf(s2);

        float px[MAXPTS], py[MAXPTS];
        int m = 0;

        // --- Edge-pair intersections (order: i-major, j-minor, as reference) ---
        #pragma unroll
        for (int ii = 0; ii < 4; ii++) {
            float x1 = p1x[ii], y1 = p1y[ii];
            float x2 = p1x[(ii + 1) & 3], y2 = p1y[(ii + 1) & 3];
            #pragma unroll
            for (int jj = 0; jj < 4; jj++) {
                float x3 = p2x[jj], y3 = p2y[jj];
                float x4 = p2x[(jj + 1) & 3], y4 = p2y[(jj + 1) & 3];

                float num   = (x1 - x2) * (y3 - y4) - (y1 - y2) * (x3 - x4);
                float den_t = (x1 - x3) * (y3 - y4) - (y1 - y3) * (x3 - x4);
                float den_u = (x2 - x1) * (y1 - y3) - (y2 - y1) * (x1 - x3);

                float t_ng = den_t / num;   // no eps, like reference (NaN/inf -> mask false)
                float u_ng = den_u / num;

                bool hit = (t_ng > 0.0f) && (t_ng < 1.0f) &&
                           (u_ng > 0.0f) && (u_ng < 1.0f);
                if (hit) {
                    float t = den_t / (num + EPSF);
                    px[m] = x1 + t * (x2 - x1);
                    py[m] = y1 + t * (y2 - y1);
                    m++;
                }
            }
        }

        // --- Vertices of poly1 inside poly2 ---
        #pragma unroll
        for (int ii = 0; ii < 4; ii++) {
            float x1 = p1x[ii], y1 = p1y[ii];
            float s = 0.0f;
            #pragma unroll
            for (int jj = 0; jj < 4; jj++) {
                float x3 = p2x[jj], y3 = p2y[jj];
                float x4 = p2x[(jj + 1) & 3], y4 = p2y[(jj + 1) & 3];
                s += fabsf((x3 - x1) * (y4 - y1) - (y3 - y1) * (x4 - x1));
            }
            s *= 0.5f;
            if (fabsf(s - area2) < 0.001f * area2) {
                px[m] = x1; py[m] = y1; m++;
            }
        }

        // --- Vertices of poly2 inside poly1 ---
        #pragma unroll
        for (int jj = 0; jj < 4; jj++) {
            float x3 = p2x[jj], y3 = p2y[jj];
            float s = 0.0f;
            #pragma unroll
            for (int ii = 0; ii < 4; ii++) {
                float x1 = p1x[ii], y1 = p1y[ii];
                float x2 = p1x[(ii + 1) & 3], y2 = p1y[(ii + 1) & 3];
                s += fabsf((x1 - x3) * (y2 - y3) - (x2 - x3) * (y1 - y3));
            }
            s *= 0.5f;
            if (fabsf(s - area1) < 0.001f * area1) {
                px[m] = x3; py[m] = y3; m++;
            }
        }

        // --- Convex area of masked points (stable sort by angle around centroid) ---
        float overlap = 0.0f;
        if (m > 0) {
            float cx = 0.0f, cy = 0.0f;
            for (int k = 0; k < m; k++) { cx += px[k]; cy += py[k]; }
            float inv_m = 1.0f / (float)m;
            cx *= inv_m; cy *= inv_m;

            float ang[MAXPTS];
            for (int k = 0; k < m; k++)
                ang[k] = atan2f(py[k] - cy, px[k] - cx);

            // stable insertion sort (strict '>' keeps equal-angle original order,
            // matching jnp.argsort stability)
            for (int k = 1; k < m; k++) {
                float ak = ang[k], xk = px[k], yk = py[k];
                int l = k - 1;
                while (l >= 0 && ang[l] > ak) {
                    ang[l + 1] = ang[l];
                    px[l + 1] = px[l];
                    py[l + 1] = py[l];
                    l--;
                }
                ang[l + 1] = ak; px[l + 1] = xk; py[l + 1] = yk;
            }

            float s = 0.0f;
            for (int k = 0; k < m; k++) {
                int k2 = (k + 1 == m) ? 0 : k + 1;
                s += px[k] * py[k2] - py[k] * px[k2];
            }
            overlap = 0.5f * fabsf(s);
        }

        float iou = overlap / (area1 + area2 - overlap + EPSF);
        iou = fminf(fmaxf(iou, EPSF), 1.0f);
        loss = 1.0f - iou;
    }

    // --- Block reduction -> one double atomic per block ---
    #pragma unroll
    for (int off = 16; off > 0; off >>= 1)
        loss += __shfl_down_sync(0xffffffffu, loss, off);

    __shared__ float wsum[TPB / 32];
    int lane = threadIdx.x & 31;
    int wid  = threadIdx.x >> 5;
    if (lane == 0) wsum[wid] = loss;
    __syncthreads();

    if (wid == 0) {
        float v = (lane < TPB / 32) ? wsum[lane] : 0.0f;
        #pragma unroll
        for (int off = 4; off > 0; off >>= 1)
            v += __shfl_down_sync(0xffffffffu, v, off);
        if (lane == 0)
            atomicAdd(&g_acc, (double)v);
    }
}

extern "C" void kernel_launch(void* const* d_in, const int* in_sizes, int n_in,
                              void* d_out, int out_size) {
    const float* pred = (const float*)d_in[0];
    const float* tgt  = (const float*)d_in[1];
    int n = in_sizes[0] / 8;

    pil_init_kernel<<<1, 1>>>();
    int blocks = (n + TPB - 1) / TPB;
    poly_iou_kernel<<<blocks, TPB>>>(pred, tgt, n);
    pil_finalize_kernel<<<1, 1>>>((float*)d_out, n);
}

// round 2
// speedup vs baseline: 1.0391x; 1.0391x over previous
#include <cuda_runtime.h>

#define EPSF 1e-6f
#define MAXPTS 16
#define TPB 256
#define MAXBLOCKS 2048

__device__ float g_partial[MAXBLOCKS];
__device__ unsigned int g_count = 0;   // wraps back to 0 every launch -> replay-safe

__device__ __forceinline__ float fast_rcp(float x) {
    float r;
    asm("rcp.approx.f32 %0, %1;" : "=f"(r) : "f"(x));
    return r;
}

__global__ __launch_bounds__(TPB)
void poly_iou_kernel(const float* __restrict__ pred,
                     const float* __restrict__ tgt,
                     float* __restrict__ out,
                     int n) {
    int i = blockIdx.x * blockDim.x + threadIdx.x;
    float loss = 0.0f;

    if (i < n) {
        float4 a0 = reinterpret_cast<const float4*>(pred)[2 * i];
        float4 a1 = reinterpret_cast<const float4*>(pred)[2 * i + 1];
        float4 b0 = reinterpret_cast<const float4*>(tgt)[2 * i];
        float4 b1 = reinterpret_cast<const float4*>(tgt)[2 * i + 1];

        float p1x[4] = {a0.x, a0.z, a1.x, a1.z};
        float p1y[4] = {a0.y, a0.w, a1.y, a1.w};
        float p2x[4] = {b0.x, b0.z, b1.x, b1.z};
        float p2y[4] = {b0.y, b0.w, b1.y, b1.w};

        // Shoelace areas (roll(+1) order as reference).
        float s1 = 0.0f, s2 = 0.0f;
        #pragma unroll
        for (int k = 0; k < 4; k++) {
            int km = (k + 3) & 3;
            s1 += p1x[k] * p1y[km] - p1x[km] * p1y[k];
            s2 += p2x[k] * p2y[km] - p2x[km] * p2y[k];
        }
        float area1 = 0.5f * fabsf(s1);
        float area2 = 0.5f * fabsf(s2);

        float px[MAXPTS], py[MAXPTS];
        int m = 0;

        // --- Edge-pair intersections (i-major, j-minor: reference order) ---
        #pragma unroll
        for (int ii = 0; ii < 4; ii++) {
            float x1 = p1x[ii], y1 = p1y[ii];
            float x2 = p1x[(ii + 1) & 3], y2 = p1y[(ii + 1) & 3];
            #pragma unroll
            for (int jj = 0; jj < 4; jj++) {
                float x3 = p2x[jj], y3 = p2y[jj];
                float x4 = p2x[(jj + 1) & 3], y4 = p2y[(jj + 1) & 3];

                float num   = (x1 - x2) * (y3 - y4) - (y1 - y2) * (x3 - x4);
                float den_t = (x1 - x3) * (y3 - y4) - (y1 - y3) * (x3 - x4);
                float den_u = (x2 - x1) * (y1 - y3) - (y2 - y1) * (x1 - x3);

                // one rcp serves both tests; num=0 -> inf/NaN -> compares false
                float rnum = fast_rcp(num);
                float t_ng = den_t * rnum;
                float u_ng = den_u * rnum;

                bool hit = (t_ng > 0.0f) && (t_ng < 1.0f) &&
                           (u_ng > 0.0f) && (u_ng < 1.0f);
                if (hit) {
                    float t = den_t * fast_rcp(num + EPSF);
                    px[m] = x1 + t * (x2 - x1);
                    py[m] = y1 + t * (y2 - y1);
                    m++;
                }
            }
        }

        // --- Vertices of poly1 inside poly2 ---
        #pragma unroll
        for (int ii = 0; ii < 4; ii++) {
            float x1 = p1x[ii], y1 = p1y[ii];
            float s = 0.0f;
            #pragma unroll
            for (int jj = 0; jj < 4; jj++) {
                float x3 = p2x[jj], y3 = p2y[jj];
                float x4 = p2x[(jj + 1) & 3], y4 = p2y[(jj + 1) & 3];
                s += fabsf((x3 - x1) * (y4 - y1) - (y3 - y1) * (x4 - x1));
            }
            s *= 0.5f;
            if (fabsf(s - area2) < 0.001f * area2) {
                px[m] = x1; py[m] = y1; m++;
            }
        }

        // --- Vertices of poly2 inside poly1 ---
        #pragma unroll
        for (int jj = 0; jj < 4; jj++) {
            float x3 = p2x[jj], y3 = p2y[jj];
            float s = 0.0f;
            #pragma unroll
            for (int ii = 0; ii < 4; ii++) {
                float x1 = p1x[ii], y1 = p1y[ii];
                float x2 = p1x[(ii + 1) & 3], y2 = p1y[(ii + 1) & 3];
                s += fabsf((x1 - x3) * (y2 - y3) - (x2 - x3) * (y1 - y3));
            }
            s *= 0.5f;
            if (fabsf(s - area1) < 0.001f * area1) {
                px[m] = x3; py[m] = y3; m++;
            }
        }

        // --- Convex area: stable sort by pseudo-angle (monotone with atan2) ---
        float overlap = 0.0f;
        if (m > 0) {
            float cx = 0.0f, cy = 0.0f;
            for (int k = 0; k < m; k++) { cx += px[k]; cy += py[k]; }
            float inv_m = 1.0f / (float)m;
            cx *= inv_m; cy *= inv_m;

            float ang[MAXPTS];
            for (int k = 0; k < m; k++) {
                float dx = px[k] - cx, dy = py[k] - cy;
                // t in [-1,1], monotone with angle within each half-plane
                float t = dy * fast_rcp(fabsf(dx) + fabsf(dy));
                // map to [-2,2], strictly increasing with atan2(dy,dx)
                float key;
                if (dx >= 0.0f)      key = t;            // angle in [-pi/2, pi/2]
                else if (dy >= 0.0f) key = 2.0f - t;     // angle in (pi/2, pi]
                else                 key = -2.0f - t;    // angle in (-pi, -pi/2)
                ang[k] = key;
            }

            // stable insertion sort (strict '>' preserves original order on ties)
            for (int k = 1; k < m; k++) {
                float ak = ang[k], xk = px[k], yk = py[k];
                int l = k - 1;
                while (l >= 0 && ang[l] > ak) {
                    ang[l + 1] = ang[l];
                    px[l + 1] = px[l];
                    py[l + 1] = py[l];
                    l--;
                }
                ang[l + 1] = ak; px[l + 1] = xk; py[l + 1] = yk;
            }

            float s = 0.0f;
            for (int k = 0; k < m; k++) {
                int k2 = (k + 1 == m) ? 0 : k + 1;
                s += px[k] * py[k2] - py[k] * px[k2];
            }
            overlap = 0.5f * fabsf(s);
        }

        float iou = overlap * fast_rcp(area1 + area2 - overlap + EPSF);
        iou = fminf(fmaxf(iou, EPSF), 1.0f);
        loss = 1.0f - iou;
    }

    // --- Intra-block reduction ---
    #pragma unroll
    for (int off = 16; off > 0; off >>= 1)
        loss += __shfl_down_sync(0xffffffffu, loss, off);

    __shared__ float wsum[TPB / 32];
    int lane = threadIdx.x & 31;
    int wid  = threadIdx.x >> 5;
    if (lane == 0) wsum[wid] = loss;
    __syncthreads();

    if (wid == 0) {
        float v = (lane < TPB / 32) ? wsum[lane] : 0.0f;
        #pragma unroll
        for (int off = 4; off > 0; off >>= 1)
            v += __shfl_down_sync(0xffffffffu, v, off);
        if (lane == 0) wsum[0] = v;
    }
    __syncthreads();

    // --- Last-block-done final reduction (single kernel, replay-safe) ---
    __shared__ bool is_last;
    if (threadIdx.x == 0) {
        g_partial[blockIdx.x] = wsum[0];
        __threadfence();
        unsigned prev = atomicInc(&g_count, gridDim.x - 1);  // wraps to 0
        is_last = (prev == gridDim.x - 1);
    }
    __syncthreads();

    if (is_last) {
        double s = 0.0;
        for (int k = threadIdx.x; k < (int)gridDim.x; k += TPB)
            s += (double)g_partial[k];
        #pragma unroll
        for (int off = 16; off > 0; off >>= 1)
            s += __shfl_down_sync(0xffffffffu, s, off);

        __shared__ double dsum[TPB / 32];
        if (lane == 0) dsum[wid] = s;
        __syncthreads();
        if (wid == 0) {
            double v = (lane < TPB / 32) ? dsum[lane] : 0.0;
            #pragma unroll
            for (int off = 4; off > 0; off >>= 1)
                v += __shfl_down_sync(0xffffffffu, v, off);
            if (lane == 0)
                out[0] = (float)(v / (double)n);
        }
    }
}

extern "C" void kernel_launch(void* const* d_in, const int* in_sizes, int n_in,
                              void* d_out, int out_size) {
    const float* pred = (const float*)d_in[0];
    const float* tgt  = (const float*)d_in[1];
    int n = in_sizes[0] / 8;

    int blocks = (n + TPB - 1) / TPB;
    poly_iou_kernel<<<blocks, TPB>>>(pred, tgt, (float*)d_out, n);
}